// round 13
// baseline (speedup 1.0000x reference)
#include <cuda_runtime.h>
#include <cuda_fp16.h>
#include <cstdint>
#include <math.h>

#define T_TOK 1024
#define H_DIM 1024
#define N_EXP 8
#define I_DIM 1024
#define ALPHA 1.702f
#define LIMIT 7.0f

// ---------------- device scratch (no allocations allowed) --------------------
// g_cnt[0..7] = per-expert token counts, g_cnt[8] = convert ticket
__device__ int      g_cnt[16];
__device__ int      g_tok[N_EXP * T_TOK];
__device__ float    g_wt [N_EXP * T_TOK];
// fp16 operand planes, packed 2 elems per u32
__device__ __align__(16) uint32_t g_x_f16  [(size_t)T_TOK * H_DIM / 2];
__device__ __align__(16) uint32_t g_gup_f16[(size_t)N_EXP * H_DIM * 2 * I_DIM / 2];
__device__ __align__(16) uint32_t g_dwn_f16[(size_t)N_EXP * I_DIM * H_DIM / 2];
__device__ __align__(16) uint32_t g_act_f16[(size_t)N_EXP * T_TOK * I_DIM / 2];
__device__ __align__(16) uint32_t g_upc_f16[(size_t)N_EXP * T_TOK * I_DIM / 2]; // clip(up)+1

// ---------------- helpers ----------------------------------------------------
__device__ __forceinline__ uint32_t smem_u32(const void* p) {
    uint32_t a;
    asm("{ .reg .u64 t; cvta.to.shared.u64 t, %1; cvt.u32.u64 %0, t; }"
        : "=r"(a) : "l"(p));
    return a;
}
__device__ __forceinline__ uint32_t swz128(uint32_t off) { return off ^ ((off >> 3) & 0x70); }
__device__ __forceinline__ uint32_t swz64 (uint32_t off) { return off ^ ((off >> 3) & 0x30); }

__device__ __forceinline__ uint32_t pack_f16x2(float a, float b) {
    uint32_t r;
    asm("cvt.rn.f16x2.f32 %0, %1, %2;" : "=r"(r) : "f"(b), "f"(a));  // a -> low half
    return r;
}

__device__ __forceinline__ void ldsm4(uint32_t* r, uint32_t a) {
    asm volatile("ldmatrix.sync.aligned.m8n8.x4.shared.b16 {%0,%1,%2,%3}, [%4];"
        : "=r"(r[0]), "=r"(r[1]), "=r"(r[2]), "=r"(r[3]) : "r"(a));
}
__device__ __forceinline__ void ldsm4t(uint32_t* r, uint32_t a) {
    asm volatile("ldmatrix.sync.aligned.m8n8.x4.trans.shared.b16 {%0,%1,%2,%3}, [%4];"
        : "=r"(r[0]), "=r"(r[1]), "=r"(r[2]), "=r"(r[3]) : "r"(a));
}
__device__ __forceinline__ void mma16816(float* c, const uint32_t* a, uint32_t b0, uint32_t b1) {
    asm volatile("mma.sync.aligned.m16n8k16.row.col.f32.f16.f16.f32 "
        "{%0,%1,%2,%3}, {%4,%5,%6,%7}, {%8,%9}, {%0,%1,%2,%3};"
        : "+f"(c[0]), "+f"(c[1]), "+f"(c[2]), "+f"(c[3])
        : "r"(a[0]), "r"(a[1]), "r"(a[2]), "r"(a[3]), "r"(b0), "r"(b1));
}

#define CP16(dst, src) \
    asm volatile("cp.async.cg.shared.global [%0], [%1], 16;" :: "r"(dst), "l"(src) : "memory")
#define CP_COMMIT() asm volatile("cp.async.commit_group;" ::: "memory")
#define CP_WAIT3()  asm volatile("cp.async.wait_group 3;" ::: "memory")

// sizes in "2x float4" (32B src) units
#define NX2 (T_TOK * H_DIM / 8)
#define NG2 (N_EXP * H_DIM * 2 * I_DIM / 8)
#define ND2 (N_EXP * I_DIM * H_DIM / 8)
#define NCONV (NX2 + NG2)
#define NCV ((NCONV / 2 + 255) / 256)
#define ND_CHUNKS (ND2 / 256)

// ---------------- fused prologue: router + x/gup converts (64B/thread) -------
__global__ void prologue_kernel(const float4* __restrict__ x4,
                                const float4* __restrict__ gup,
                                const float* __restrict__ rw,
                                const float* __restrict__ rb,
                                float4* __restrict__ out) {
    const int tid = threadIdx.x;
    if (blockIdx.x < T_TOK) {
        const int t = blockIdx.x;
        out[t * 256 + tid] = make_float4(0.f, 0.f, 0.f, 0.f);

        __shared__ float s[N_EXP][256];
        __shared__ float s_log[N_EXP];
        const float* xr = (const float*)(x4) + (size_t)t * H_DIM;
        float p[N_EXP];
#pragma unroll
        for (int e = 0; e < N_EXP; e++) p[e] = 0.0f;
#pragma unroll
        for (int q = 0; q < 4; q++) {
            int h = tid + q * 256;
            float xv = xr[h];
#pragma unroll
            for (int e = 0; e < N_EXP; e++) p[e] += xv * rw[e * H_DIM + h];
        }
#pragma unroll
        for (int e = 0; e < N_EXP; e++) s[e][tid] = p[e];
        __syncthreads();
        const int wid = tid >> 5, lane = tid & 31;
        {
            float v = 0.0f;
#pragma unroll
            for (int j = 0; j < 8; j++) v += s[wid][lane + 32 * j];
#pragma unroll
            for (int o = 16; o > 0; o >>= 1) v += __shfl_xor_sync(0xFFFFFFFFu, v, o);
            if (lane == 0) s_log[wid] = v + rb[wid];
        }
        __syncthreads();
        if (tid == 0) {
            float l[N_EXP], mx = -1e30f;
#pragma unroll
            for (int e = 0; e < N_EXP; e++) { l[e] = s_log[e]; mx = fmaxf(mx, l[e]); }
            float den = 0.0f, sc[N_EXP];
#pragma unroll
            for (int e = 0; e < N_EXP; e++) { sc[e] = expf(l[e] - mx); den += sc[e]; }
            float inv = 1.0f / den;
#pragma unroll
            for (int e = 0; e < N_EXP; e++) sc[e] *= inv;
            int i0 = 0;
#pragma unroll
            for (int e = 1; e < N_EXP; e++) if (sc[e] > sc[i0]) i0 = e;
            int i1 = (i0 == 0) ? 1 : 0;
#pragma unroll
            for (int e = 0; e < N_EXP; e++) if (e != i0 && sc[e] > sc[i1]) i1 = e;
            int p0 = atomicAdd(&g_cnt[i0], 1);
            g_tok[i0 * T_TOK + p0] = t; g_wt[i0 * T_TOK + p0] = sc[i0];
            int p1 = atomicAdd(&g_cnt[i1], 1);
            g_tok[i1 * T_TOK + p1] = t; g_wt[i1 * T_TOK + p1] = sc[i1];
        }
        return;
    }
    // ---- convert x + gate_up: 64B fp32 -> 32B fp16 per thread ----
    int i = (blockIdx.x - T_TOK) * 256 + tid;      // handles units 2i, 2i+1
    int u0 = 2 * i;
    if (u0 >= NCONV) return;
    const float4* src; uint2* dst; int j;
    if (u0 < NX2) { src = x4;  dst = (uint2*)g_x_f16;   j = u0; }           // NX2 even
    else          { src = gup; dst = (uint2*)g_gup_f16; j = u0 - NX2; }
#pragma unroll
    for (int q = 0; q < 2; q++) {
        float4 v0 = src[(j + q) * 2];
        float4 v1 = src[(j + q) * 2 + 1];
        dst[(j + q) * 2]     = make_uint2(pack_f16x2(v0.x, v0.y), pack_f16x2(v0.z, v0.w));
        dst[(j + q) * 2 + 1] = make_uint2(pack_f16x2(v1.x, v1.y), pack_f16x2(v1.z, v1.w));
    }
}

// ---------------- half-GEMM: gate OR up pass (fp16, BK=32, 5-stage, occ 3) ---
// Stage (12KB): A 8KB (128 rows x 64B, SW64), B 4KB (32 k-rows x 128B, SW128)
// up_pass=1: C = x @ gup[:, I:]; epilogue stores clip(u)+1 (fp16) to g_upc.
// up_pass=0: C = x @ gup[:, :I]; epilogue: act = upc * glu(min(g,LIMIT)).
// Dead blocks convert down_proj fp32->fp16 via ticket queue.
#define HG_A      0
#define HG_B      8192
#define HG_STRIDE 12288
#define STAGES    5
#define N_ITERS   32

__global__ __launch_bounds__(256, 3)
void moe_half_gemm(const float* __restrict__ gub, const float4* __restrict__ dwn,
                   const int up_pass) {
    const int e   = blockIdx.z;
    const int cnt = g_cnt[e];
    const int m0  = blockIdx.x * 128;
    const int tid = threadIdx.x;

    if (m0 >= cnt) {
        // ---- recycled block: convert down_proj chunks ----
        __shared__ int s_c;
        uint2* dst = (uint2*)g_dwn_f16;
        for (;;) {
            if (tid == 0) s_c = atomicAdd(&g_cnt[8], 1);
            __syncthreads();
            int c = s_c;
            __syncthreads();
            if (c >= ND_CHUNKS) return;
            int j = (c * 256 + tid) * 2;
            float4 v0 = dwn[j];
            float4 v1 = dwn[j + 1];
            dst[j]     = make_uint2(pack_f16x2(v0.x, v0.y), pack_f16x2(v0.z, v0.w));
            dst[j + 1] = make_uint2(pack_f16x2(v1.x, v1.y), pack_f16x2(v1.z, v1.w));
        }
    }
    const int n0 = blockIdx.y * 64;

    extern __shared__ char dsm[];
    __shared__ int s_tok[128];
    const uint32_t dbase = (smem_u32(dsm) + 1023u) & ~1023u;

    const int lane = tid & 31, wid = tid >> 5;
    const int mw = wid >> 1, nw = wid & 1;

    if (tid < 128) {
        int gm = m0 + tid;
        s_tok[tid] = (gm < cnt) ? g_tok[e * T_TOK + gm] : g_tok[e * T_TOK];
    }
    __syncthreads();

    const int rA = tid >> 2, pA = tid & 3;
    const int tA0 = s_tok[rA], tA1 = s_tok[rA + 64];
    const int kB = tid >> 3, pB = tid & 7;
    const size_t gupb = (size_t)e * (H_DIM * I_DIM) + up_pass * 512;   // u32 units
    const uint32_t dA0 = swz64(rA * 64 + pA * 16);
    const uint32_t dA1 = swz64((rA + 64) * 64 + pA * 16);
    const uint32_t dB  = swz128(kB * 128 + pB * 16);

#define HG_ISSUE(s_) do { if ((s_) < N_ITERS) {                                              \
    uint32_t bb = dbase + ((s_) % STAGES) * HG_STRIDE;                                       \
    int kh = (s_) * 16;                                                                      \
    CP16(bb + HG_A + dA0, g_x_f16 + (size_t)tA0 * 512 + kh + pA * 4);                        \
    CP16(bb + HG_A + dA1, g_x_f16 + (size_t)tA1 * 512 + kh + pA * 4);                        \
    size_t bro = gupb + (size_t)((s_) * 32 + kB) * 1024 + (n0 >> 1) + pB * 4;                \
    CP16(bb + HG_B + dB, g_gup_f16 + bro);                                                   \
} CP_COMMIT(); } while (0)

    float cd[2][4][4];
#pragma unroll
    for (int a = 0; a < 2; a++)
#pragma unroll
        for (int b = 0; b < 4; b++)
#pragma unroll
            for (int c = 0; c < 4; c++) cd[a][b][c] = 0.f;

    HG_ISSUE(0);
    HG_ISSUE(1);
    HG_ISSUE(2);

#pragma unroll 1
    for (int it = 0; it < N_ITERS; ++it) {
        HG_ISSUE(it + 3);
        CP_WAIT3();
        __syncthreads();
        uint32_t base = dbase + (it % STAGES) * HG_STRIDE;
#pragma unroll
        for (int s = 0; s < 2; s++) {
            uint32_t am[2][4];
#pragma unroll
            for (int mt = 0; mt < 2; mt++) {
                uint32_t row = mw * 32 + mt * 16 + (lane & 15);
                uint32_t co  = s * 32 + ((lane >> 4) << 4);
                ldsm4(am[mt], base + HG_A + swz64(row * 64 + co));
            }
            uint32_t krow = s * 16 + (lane & 15);
            uint32_t ccol = nw * 64 + ((lane >> 4) << 4);
            uint32_t bb[8];
#pragma unroll
            for (int h = 0; h < 2; h++)
                ldsm4t(bb + 4 * h, base + HG_B + swz128(krow * 128 + ccol + h * 32));
#pragma unroll
            for (int mt = 0; mt < 2; mt++)
#pragma unroll
                for (int nf = 0; nf < 4; nf++)
                    mma16816(cd[mt][nf], am[mt], bb[2*nf], bb[2*nf+1]);
        }
        // single sync/iter: 5 stages, write buf (it+3)%5 != oldest read (it-1)%5
    }
#undef HG_ISSUE

    // ---- epilogue ----
    const float* bias = gub + e * 2 * I_DIM + up_pass * I_DIM;
#pragma unroll
    for (int mt = 0; mt < 2; mt++)
#pragma unroll
        for (int r = 0; r < 2; r++) {
            int slot = m0 + mw * 32 + mt * 16 + (lane >> 2) + r * 8;
            if (slot >= cnt) continue;
            size_t abase = ((size_t)(e * T_TOK + slot) * I_DIM) >> 1;
#pragma unroll
            for (int nf = 0; nf < 4; nf++) {
                int col = n0 + nw * 32 + nf * 8 + (lane & 3) * 2;
                float c0 = cd[mt][nf][2 * r]     + bias[col];
                float c1 = cd[mt][nf][2 * r + 1] + bias[col + 1];
                if (up_pass) {
                    c0 = fminf(fmaxf(c0, -LIMIT), LIMIT) + 1.0f;
                    c1 = fminf(fmaxf(c1, -LIMIT), LIMIT) + 1.0f;
                    g_upc_f16[abase + (col >> 1)] = pack_f16x2(c0, c1);
                } else {
                    c0 = fminf(c0, LIMIT);
                    c1 = fminf(c1, LIMIT);
                    float glu0 = c0 / (1.0f + __expf(-ALPHA * c0));
                    float glu1 = c1 / (1.0f + __expf(-ALPHA * c1));
                    uint32_t uv = g_upc_f16[abase + (col >> 1)];
                    __half2 uh = *reinterpret_cast<__half2*>(&uv);
                    float a0 = __low2float(uh)  * glu0;
                    float a1 = __high2float(uh) * glu1;
                    g_act_f16[abase + (col >> 1)] = pack_f16x2(a0, a1);
                }
            }
        }
}

// ---------------- kernel 3: down HMMA (fp16, BK=32, 5-stage, occ 3) ----------
#define DN_A      0
#define DN_B      8192
#define DN_STRIDE 12288

__global__ __launch_bounds__(256, 3)
void moe_down_hmma(const float* __restrict__ dnb, float* __restrict__ out) {
    const int e   = blockIdx.z;
    const int cnt = g_cnt[e];
    const int m0  = blockIdx.x * 128;
    if (m0 >= cnt) return;
    const int n0  = blockIdx.y * 64;

    extern __shared__ char dsm[];
    const uint32_t dbase = (smem_u32(dsm) + 1023u) & ~1023u;

    const int tid = threadIdx.x, lane = tid & 31, wid = tid >> 5;
    const int mw = wid >> 1, nw = wid & 1;

    const int rA = tid >> 2, pA = tid & 3;
    const int kB = tid >> 3, pB = tid & 7;
    const size_t a0 = (size_t)(e * T_TOK + m0 + rA) * 512;
    const size_t a1 = (size_t)(e * T_TOK + m0 + rA + 64) * 512;
    const size_t dwb = (size_t)e * (I_DIM * H_DIM / 2);
    const uint32_t dA0 = swz64(rA * 64 + pA * 16);
    const uint32_t dA1 = swz64((rA + 64) * 64 + pA * 16);
    const uint32_t dB  = swz128(kB * 128 + pB * 16);

#define DN_ISSUE(s_) do { if ((s_) < N_ITERS) {                                              \
    uint32_t bb = dbase + ((s_) % STAGES) * DN_STRIDE;                                       \
    int kh = (s_) * 16;                                                                      \
    CP16(bb + DN_A + dA0, g_act_f16 + a0 + kh + pA * 4);                                     \
    CP16(bb + DN_A + dA1, g_act_f16 + a1 + kh + pA * 4);                                     \
    size_t bro = dwb + (size_t)((s_) * 32 + kB) * 512 + (n0 >> 1) + pB * 4;                  \
    CP16(bb + DN_B + dB, g_dwn_f16 + bro);                                                   \
} CP_COMMIT(); } while (0)

    float cd[2][4][4];
#pragma unroll
    for (int a = 0; a < 2; a++)
#pragma unroll
        for (int b = 0; b < 4; b++)
#pragma unroll
            for (int c = 0; c < 4; c++) cd[a][b][c] = 0.f;

    DN_ISSUE(0);
    DN_ISSUE(1);
    DN_ISSUE(2);

#pragma unroll 1
    for (int it = 0; it < N_ITERS; ++it) {
        DN_ISSUE(it + 3);
        CP_WAIT3();
        __syncthreads();
        uint32_t base = dbase + (it % STAGES) * DN_STRIDE;
#pragma unroll
        for (int s = 0; s < 2; s++) {
            uint32_t am[2][4];
#pragma unroll
            for (int mt = 0; mt < 2; mt++) {
                uint32_t row = mw * 32 + mt * 16 + (lane & 15);
                uint32_t co  = s * 32 + ((lane >> 4) << 4);
                ldsm4(am[mt], base + DN_A + swz64(row * 64 + co));
            }
            uint32_t krow = s * 16 + (lane & 15);
            uint32_t ccol = nw * 64 + ((lane >> 4) << 4);
            uint32_t bb[8];
#pragma unroll
            for (int h = 0; h < 2; h++)
                ldsm4t(bb + 4 * h, base + DN_B + swz128(krow * 128 + ccol + h * 32));
#pragma unroll
            for (int mt = 0; mt < 2; mt++)
#pragma unroll
                for (int nf = 0; nf < 4; nf++)
                    mma16816(cd[mt][nf], am[mt], bb[2*nf], bb[2*nf+1]);
        }
    }
#undef DN_ISSUE

    const float* db = dnb + e * H_DIM;
#pragma unroll
    for (int mt = 0; mt < 2; mt++)
#pragma unroll
        for (int r = 0; r < 2; r++) {
            int slot = m0 + mw * 32 + mt * 16 + (lane >> 2) + r * 8;
            if (slot >= cnt) continue;
            int   tok = g_tok[e * T_TOK + slot];
            float w   = g_wt [e * T_TOK + slot];
            float* op = out + (size_t)tok * H_DIM;
#pragma unroll
            for (int nf = 0; nf < 4; nf++) {
                int col = n0 + nw * 32 + nf * 8 + (lane & 3) * 2;
                float v0 = (cd[mt][nf][2 * r]     + db[col])     * w;
                float v1 = (cd[mt][nf][2 * r + 1] + db[col + 1]) * w;
                atomicAdd(op + col,     v0);
                atomicAdd(op + col + 1, v1);
            }
        }
}

// ---------------- launch -----------------------------------------------------
extern "C" void kernel_launch(void* const* d_in, const int* in_sizes, int n_in,
                              void* d_out, int out_size) {
    const float* x   = (const float*)d_in[0];
    const float* rw  = (const float*)d_in[1];
    const float* rb  = (const float*)d_in[2];
    const float* gup = (const float*)d_in[3];
    const float* gub = (const float*)d_in[4];
    const float* dwn = (const float*)d_in[5];
    const float* dnb = (const float*)d_in[6];
    float* out = (float*)d_out;

    static bool attr_done = false;
    static void* cnt_addr = nullptr;
    if (!attr_done) {
        cudaFuncSetAttribute(moe_half_gemm, cudaFuncAttributeMaxDynamicSharedMemorySize,
                             STAGES * HG_STRIDE + 1024);
        cudaFuncSetAttribute(moe_down_hmma, cudaFuncAttributeMaxDynamicSharedMemorySize,
                             STAGES * DN_STRIDE + 1024);
        cudaGetSymbolAddress(&cnt_addr, g_cnt);
        attr_done = true;
    }

    cudaMemsetAsync(cnt_addr, 0, 16 * sizeof(int));

    prologue_kernel<<<T_TOK + NCV, 256>>>((const float4*)x, (const float4*)gup,
                                          rw, rb, (float4*)out);

    dim3 g1(T_TOK / 128, I_DIM / 64, N_EXP);
    moe_half_gemm<<<g1, 256, STAGES * HG_STRIDE + 1024>>>(gub, (const float4*)dwn, 1);
    moe_half_gemm<<<g1, 256, STAGES * HG_STRIDE + 1024>>>(gub, (const float4*)dwn, 0);

    dim3 g2(T_TOK / 128, H_DIM / 64, N_EXP);
    moe_down_hmma<<<g2, 256, STAGES * DN_STRIDE + 1024>>>(dnb, out);
}

// round 15
// speedup vs baseline: 1.1320x; 1.1320x over previous
#include <cuda_runtime.h>
#include <cstdint>
#include <math.h>

#define T_TOK 1024
#define H_DIM 1024
#define N_EXP 8
#define I_DIM 1024
#define ALPHA 1.702f
#define LIMIT 7.0f

// ---------------- device scratch (no allocations allowed) --------------------
// g_cnt[0..7] = per-expert token counts, g_cnt[8] = convert ticket
__device__ int      g_cnt[16];
__device__ int      g_tok[N_EXP * T_TOK];
__device__ float    g_wt [N_EXP * T_TOK];
// fp16 operand planes, packed 2 elems per u32
__device__ __align__(16) uint32_t g_x_f16  [(size_t)T_TOK * H_DIM / 2];
__device__ __align__(16) uint32_t g_gup_f16[(size_t)N_EXP * H_DIM * 2 * I_DIM / 2];
__device__ __align__(16) uint32_t g_dwn_f16[(size_t)N_EXP * I_DIM * H_DIM / 2];
__device__ __align__(16) uint32_t g_act_f16[(size_t)N_EXP * T_TOK * I_DIM / 2];

// ---------------- helpers ----------------------------------------------------
__device__ __forceinline__ uint32_t smem_u32(const void* p) {
    uint32_t a;
    asm("{ .reg .u64 t; cvta.to.shared.u64 t, %1; cvt.u32.u64 %0, t; }"
        : "=r"(a) : "l"(p));
    return a;
}
__device__ __forceinline__ uint32_t swz128(uint32_t off) { return off ^ ((off >> 3) & 0x70); }
__device__ __forceinline__ uint32_t swz64 (uint32_t off) { return off ^ ((off >> 3) & 0x30); }

__device__ __forceinline__ uint32_t pack_f16x2(float a, float b) {
    uint32_t r;
    asm("cvt.rn.f16x2.f32 %0, %1, %2;" : "=r"(r) : "f"(b), "f"(a));  // a -> low half
    return r;
}

__device__ __forceinline__ void ldsm4(uint32_t* r, uint32_t a) {
    asm volatile("ldmatrix.sync.aligned.m8n8.x4.shared.b16 {%0,%1,%2,%3}, [%4];"
        : "=r"(r[0]), "=r"(r[1]), "=r"(r[2]), "=r"(r[3]) : "r"(a));
}
__device__ __forceinline__ void ldsm4t(uint32_t* r, uint32_t a) {
    asm volatile("ldmatrix.sync.aligned.m8n8.x4.trans.shared.b16 {%0,%1,%2,%3}, [%4];"
        : "=r"(r[0]), "=r"(r[1]), "=r"(r[2]), "=r"(r[3]) : "r"(a));
}
__device__ __forceinline__ void mma16816(float* c, const uint32_t* a, uint32_t b0, uint32_t b1) {
    asm volatile("mma.sync.aligned.m16n8k16.row.col.f32.f16.f16.f32 "
        "{%0,%1,%2,%3}, {%4,%5,%6,%7}, {%8,%9}, {%0,%1,%2,%3};"
        : "+f"(c[0]), "+f"(c[1]), "+f"(c[2]), "+f"(c[3])
        : "r"(a[0]), "r"(a[1]), "r"(a[2]), "r"(a[3]), "r"(b0), "r"(b1));
}

#define CP16(dst, src) \
    asm volatile("cp.async.cg.shared.global [%0], [%1], 16;" :: "r"(dst), "l"(src) : "memory")
#define CP_COMMIT() asm volatile("cp.async.commit_group;" ::: "memory")
#define CP_WAIT3()  asm volatile("cp.async.wait_group 3;" ::: "memory")

// sizes in "2x float4" (32B src) units
#define NX2 (T_TOK * H_DIM / 8)
#define NG2 (N_EXP * H_DIM * 2 * I_DIM / 8)
#define ND2 (N_EXP * I_DIM * H_DIM / 8)
#define NCV ((NX2 + NG2 + 255) / 256)
#define ND_CHUNKS (ND2 / 256)

// ---------------- fused prologue: router + x/gup converts --------------------
__global__ void prologue_kernel(const float4* __restrict__ x4,
                                const float4* __restrict__ gup,
                                const float* __restrict__ rw,
                                const float* __restrict__ rb,
                                float4* __restrict__ out) {
    const int tid = threadIdx.x;
    if (blockIdx.x < T_TOK) {
        // ---- router for token t (256 threads) + zero out row ----
        const int t = blockIdx.x;
        out[t * 256 + tid] = make_float4(0.f, 0.f, 0.f, 0.f);

        __shared__ float s[N_EXP][256];
        __shared__ float s_log[N_EXP];
        const float* xr = (const float*)(x4) + (size_t)t * H_DIM;
        float p[N_EXP];
#pragma unroll
        for (int e = 0; e < N_EXP; e++) p[e] = 0.0f;
#pragma unroll
        for (int q = 0; q < 4; q++) {
            int h = tid + q * 256;
            float xv = xr[h];
#pragma unroll
            for (int e = 0; e < N_EXP; e++) p[e] += xv * rw[e * H_DIM + h];
        }
#pragma unroll
        for (int e = 0; e < N_EXP; e++) s[e][tid] = p[e];
        __syncthreads();
        const int wid = tid >> 5, lane = tid & 31;
        {
            float v = 0.0f;
#pragma unroll
            for (int j = 0; j < 8; j++) v += s[wid][lane + 32 * j];
#pragma unroll
            for (int o = 16; o > 0; o >>= 1) v += __shfl_xor_sync(0xFFFFFFFFu, v, o);
            if (lane == 0) s_log[wid] = v + rb[wid];
        }
        __syncthreads();
        if (tid == 0) {
            float l[N_EXP], mx = -1e30f;
#pragma unroll
            for (int e = 0; e < N_EXP; e++) { l[e] = s_log[e]; mx = fmaxf(mx, l[e]); }
            float den = 0.0f, sc[N_EXP];
#pragma unroll
            for (int e = 0; e < N_EXP; e++) { sc[e] = expf(l[e] - mx); den += sc[e]; }
            float inv = 1.0f / den;
#pragma unroll
            for (int e = 0; e < N_EXP; e++) sc[e] *= inv;
            int i0 = 0;
#pragma unroll
            for (int e = 1; e < N_EXP; e++) if (sc[e] > sc[i0]) i0 = e;
            int i1 = (i0 == 0) ? 1 : 0;
#pragma unroll
            for (int e = 0; e < N_EXP; e++) if (e != i0 && sc[e] > sc[i1]) i1 = e;
            int p0 = atomicAdd(&g_cnt[i0], 1);
            g_tok[i0 * T_TOK + p0] = t; g_wt[i0 * T_TOK + p0] = sc[i0];
            int p1 = atomicAdd(&g_cnt[i1], 1);
            g_tok[i1 * T_TOK + p1] = t; g_wt[i1 * T_TOK + p1] = sc[i1];
        }
        return;
    }
    // ---- convert x + gate_up: 32B fp32 -> 16B fp16 per thread ----
    int i = (blockIdx.x - T_TOK) * 256 + tid;
    if (i >= NX2 + NG2) return;
    const float4* src; uint2* dst; int j;
    if (i < NX2) { src = x4;  dst = (uint2*)g_x_f16;   j = i; }
    else         { src = gup; dst = (uint2*)g_gup_f16; j = i - NX2; }
    j *= 2;
    float4 v0 = src[j];
    float4 v1 = src[j + 1];
    dst[j]     = make_uint2(pack_f16x2(v0.x, v0.y), pack_f16x2(v0.z, v0.w));
    dst[j + 1] = make_uint2(pack_f16x2(v1.x, v1.y), pack_f16x2(v1.z, v1.w));
}

// ---------------- kernel 2: gate_up HMMA (fp16, BK=32, 5-stage, depth-3) -----
// Stage (16KB): A 8KB (128 rows x 64B, SW64), BG 4KB, BU 4KB (32 k-rows x 128B, SW128)
// Dead blocks (m0 >= cnt) convert down_proj fp32->fp16 via ticket queue.
// Inner loop: ALL LDSM for both s-phases issued first, then all MMAs.
#define GU_A      0
#define GU_BG     8192
#define GU_BU     12288
#define GU_STRIDE 16384
#define STAGES    5
#define N_ITERS   32

__global__ __launch_bounds__(256, 2)
void moe_gateup_hmma(const float* __restrict__ gub, const float4* __restrict__ dwn) {
    const int e   = blockIdx.z;
    const int cnt = g_cnt[e];
    const int m0  = blockIdx.x * 128;
    const int tid = threadIdx.x;

    if (m0 >= cnt) {
        // ---- recycled block: convert down_proj chunks ----
        __shared__ int s_c;
        uint2* dst = (uint2*)g_dwn_f16;
        for (;;) {
            if (tid == 0) s_c = atomicAdd(&g_cnt[8], 1);
            __syncthreads();
            int c = s_c;
            __syncthreads();
            if (c >= ND_CHUNKS) return;
            int j = (c * 256 + tid) * 2;
            float4 v0 = dwn[j];
            float4 v1 = dwn[j + 1];
            dst[j]     = make_uint2(pack_f16x2(v0.x, v0.y), pack_f16x2(v0.z, v0.w));
            dst[j + 1] = make_uint2(pack_f16x2(v1.x, v1.y), pack_f16x2(v1.z, v1.w));
        }
    }
    const int n0 = blockIdx.y * 64;

    extern __shared__ char dsm[];
    __shared__ int s_tok[128];
    const uint32_t dbase = (smem_u32(dsm) + 1023u) & ~1023u;

    const int lane = tid & 31, wid = tid >> 5;
    const int mw = wid >> 1, nw = wid & 1;

    if (tid < 128) {
        int gm = m0 + tid;
        s_tok[tid] = (gm < cnt) ? g_tok[e * T_TOK + gm] : g_tok[e * T_TOK];
    }
    __syncthreads();

    const int rA = tid >> 2, pA = tid & 3;
    const int tA0 = s_tok[rA], tA1 = s_tok[rA + 64];
    const int kB = tid >> 3, pB = tid & 7;
    const size_t gupb = (size_t)e * (H_DIM * I_DIM);
    const uint32_t dA0 = swz64(rA * 64 + pA * 16);
    const uint32_t dA1 = swz64((rA + 64) * 64 + pA * 16);
    const uint32_t dB  = swz128(kB * 128 + pB * 16);

#define GU_ISSUE(s_) do { if ((s_) < N_ITERS) {                                              \
    uint32_t bb = dbase + ((s_) % STAGES) * GU_STRIDE;                                       \
    int kh = (s_) * 16;                                                                      \
    CP16(bb + GU_A + dA0, g_x_f16 + (size_t)tA0 * 512 + kh + pA * 4);                        \
    CP16(bb + GU_A + dA1, g_x_f16 + (size_t)tA1 * 512 + kh + pA * 4);                        \
    size_t bro = gupb + (size_t)((s_) * 32 + kB) * 1024 + (n0 >> 1) + pB * 4;                \
    CP16(bb + GU_BG + dB, g_gup_f16 + bro);                                                  \
    CP16(bb + GU_BU + dB, g_gup_f16 + bro + 512);                                            \
} CP_COMMIT(); } while (0)

    float cg[2][4][4], cu[2][4][4];
#pragma unroll
    for (int a = 0; a < 2; a++)
#pragma unroll
        for (int b = 0; b < 4; b++)
#pragma unroll
            for (int c = 0; c < 4; c++) { cg[a][b][c] = 0.f; cu[a][b][c] = 0.f; }

    GU_ISSUE(0);
    GU_ISSUE(1);
    GU_ISSUE(2);

#pragma unroll 1
    for (int it = 0; it < N_ITERS; ++it) {
        GU_ISSUE(it + 3);
        CP_WAIT3();
        __syncthreads();
        uint32_t base = dbase + (it % STAGES) * GU_STRIDE;

        // ---- issue ALL fragment loads for both s-phases first ----
        uint32_t am[2][2][4];    // [s][mt]
        uint32_t bg[2][8], bu[2][8];
#pragma unroll
        for (int s = 0; s < 2; s++) {
            uint32_t co  = s * 32 + ((lane >> 4) << 4);
#pragma unroll
            for (int mt = 0; mt < 2; mt++) {
                uint32_t row = mw * 32 + mt * 16 + (lane & 15);
                ldsm4(am[s][mt], base + GU_A + swz64(row * 64 + co));
            }
            uint32_t krow = s * 16 + (lane & 15);
            uint32_t ccol = nw * 64 + ((lane >> 4) << 4);
#pragma unroll
            for (int h = 0; h < 2; h++) {
                ldsm4t(bg[s] + 4 * h, base + GU_BG + swz128(krow * 128 + ccol + h * 32));
                ldsm4t(bu[s] + 4 * h, base + GU_BU + swz128(krow * 128 + ccol + h * 32));
            }
        }
        // ---- then all MMAs ----
#pragma unroll
        for (int s = 0; s < 2; s++)
#pragma unroll
            for (int mt = 0; mt < 2; mt++)
#pragma unroll
                for (int nf = 0; nf < 4; nf++) {
                    mma16816(cg[mt][nf], am[s][mt], bg[s][2*nf], bg[s][2*nf+1]);
                    mma16816(cu[mt][nf], am[s][mt], bu[s][2*nf], bu[s][2*nf+1]);
                }
        // single sync/iter: 5 stages, write buf (it+3)%5 != oldest read (it-1)%5
    }
#undef GU_ISSUE

    // epilogue: bias + clamped GLU -> g_act (packed fp16)
    const float* gb = gub + e * 2 * I_DIM;
#pragma unroll
    for (int mt = 0; mt < 2; mt++)
#pragma unroll
        for (int r = 0; r < 2; r++) {
            int slot = m0 + mw * 32 + mt * 16 + (lane >> 2) + r * 8;
            if (slot >= cnt) continue;
            size_t abase = ((size_t)(e * T_TOK + slot) * I_DIM) >> 1;
#pragma unroll
            for (int nf = 0; nf < 4; nf++) {
                int col = n0 + nw * 32 + nf * 8 + (lane & 3) * 2;
                float g0 = cg[mt][nf][2 * r]     + gb[col];
                float g1 = cg[mt][nf][2 * r + 1] + gb[col + 1];
                float u0 = cu[mt][nf][2 * r]     + gb[I_DIM + col];
                float u1 = cu[mt][nf][2 * r + 1] + gb[I_DIM + col + 1];
                g0 = fminf(g0, LIMIT); g1 = fminf(g1, LIMIT);
                u0 = fminf(fmaxf(u0, -LIMIT), LIMIT);
                u1 = fminf(fmaxf(u1, -LIMIT), LIMIT);
                float a0 = (u0 + 1.0f) * (g0 / (1.0f + __expf(-ALPHA * g0)));
                float a1 = (u1 + 1.0f) * (g1 / (1.0f + __expf(-ALPHA * g1)));
                g_act_f16[abase + (col >> 1)] = pack_f16x2(a0, a1);
            }
        }
}

// ---------------- kernel 3: down HMMA (fp16, BK=32, 5-stage, depth-3) --------
// Stage (12KB): A 8KB (SW64), B 4KB (SW128). LDSM-batched inner loop.
#define DN_A      0
#define DN_B      8192
#define DN_STRIDE 12288

__global__ __launch_bounds__(256, 2)
void moe_down_hmma(const float* __restrict__ dnb, float* __restrict__ out) {
    const int e   = blockIdx.z;
    const int cnt = g_cnt[e];
    const int m0  = blockIdx.x * 128;
    if (m0 >= cnt) return;
    const int n0  = blockIdx.y * 64;

    extern __shared__ char dsm[];
    const uint32_t dbase = (smem_u32(dsm) + 1023u) & ~1023u;

    const int tid = threadIdx.x, lane = tid & 31, wid = tid >> 5;
    const int mw = wid >> 1, nw = wid & 1;

    const int rA = tid >> 2, pA = tid & 3;
    const int kB = tid >> 3, pB = tid & 7;
    const size_t a0 = (size_t)(e * T_TOK + m0 + rA) * 512;
    const size_t a1 = (size_t)(e * T_TOK + m0 + rA + 64) * 512;
    const size_t dwb = (size_t)e * (I_DIM * H_DIM / 2);
    const uint32_t dA0 = swz64(rA * 64 + pA * 16);
    const uint32_t dA1 = swz64((rA + 64) * 64 + pA * 16);
    const uint32_t dB  = swz128(kB * 128 + pB * 16);

#define DN_ISSUE(s_) do { if ((s_) < N_ITERS) {                                              \
    uint32_t bb = dbase + ((s_) % STAGES) * DN_STRIDE;                                       \
    int kh = (s_) * 16;                                                                      \
    CP16(bb + DN_A + dA0, g_act_f16 + a0 + kh + pA * 4);                                     \
    CP16(bb + DN_A + dA1, g_act_f16 + a1 + kh + pA * 4);                                     \
    size_t bro = dwb + (size_t)((s_) * 32 + kB) * 512 + (n0 >> 1) + pB * 4;                  \
    CP16(bb + DN_B + dB, g_dwn_f16 + bro);                                                   \
} CP_COMMIT(); } while (0)

    float cd[2][4][4];
#pragma unroll
    for (int a = 0; a < 2; a++)
#pragma unroll
        for (int b = 0; b < 4; b++)
#pragma unroll
            for (int c = 0; c < 4; c++) cd[a][b][c] = 0.f;

    DN_ISSUE(0);
    DN_ISSUE(1);
    DN_ISSUE(2);

#pragma unroll 1
    for (int it = 0; it < N_ITERS; ++it) {
        DN_ISSUE(it + 3);
        CP_WAIT3();
        __syncthreads();
        uint32_t base = dbase + (it % STAGES) * DN_STRIDE;

        uint32_t am[2][2][4];   // [s][mt]
        uint32_t bb[2][8];
#pragma unroll
        for (int s = 0; s < 2; s++) {
            uint32_t co  = s * 32 + ((lane >> 4) << 4);
#pragma unroll
            for (int mt = 0; mt < 2; mt++) {
                uint32_t row = mw * 32 + mt * 16 + (lane & 15);
                ldsm4(am[s][mt], base + DN_A + swz64(row * 64 + co));
            }
            uint32_t krow = s * 16 + (lane & 15);
            uint32_t ccol = nw * 64 + ((lane >> 4) << 4);
#pragma unroll
            for (int h = 0; h < 2; h++)
                ldsm4t(bb[s] + 4 * h, base + DN_B + swz128(krow * 128 + ccol + h * 32));
        }
#pragma unroll
        for (int s = 0; s < 2; s++)
#pragma unroll
            for (int mt = 0; mt < 2; mt++)
#pragma unroll
                for (int nf = 0; nf < 4; nf++)
                    mma16816(cd[mt][nf], am[s][mt], bb[s][2*nf], bb[s][2*nf+1]);
    }
#undef DN_ISSUE

    const float* db = dnb + e * H_DIM;
#pragma unroll
    for (int mt = 0; mt < 2; mt++)
#pragma unroll
        for (int r = 0; r < 2; r++) {
            int slot = m0 + mw * 32 + mt * 16 + (lane >> 2) + r * 8;
            if (slot >= cnt) continue;
            int   tok = g_tok[e * T_TOK + slot];
            float w   = g_wt [e * T_TOK + slot];
            float* op = out + (size_t)tok * H_DIM;
#pragma unroll
            for (int nf = 0; nf < 4; nf++) {
                int col = n0 + nw * 32 + nf * 8 + (lane & 3) * 2;
                float v0 = (cd[mt][nf][2 * r]     + db[col])     * w;
                float v1 = (cd[mt][nf][2 * r + 1] + db[col + 1]) * w;
                atomicAdd(op + col,     v0);
                atomicAdd(op + col + 1, v1);
            }
        }
}

// ---------------- launch -----------------------------------------------------
extern "C" void kernel_launch(void* const* d_in, const int* in_sizes, int n_in,
                              void* d_out, int out_size) {
    const float* x   = (const float*)d_in[0];
    const float* rw  = (const float*)d_in[1];
    const float* rb  = (const float*)d_in[2];
    const float* gup = (const float*)d_in[3];
    const float* gub = (const float*)d_in[4];
    const float* dwn = (const float*)d_in[5];
    const float* dnb = (const float*)d_in[6];
    float* out = (float*)d_out;

    static bool attr_done = false;
    static void* cnt_addr = nullptr;
    if (!attr_done) {
        cudaFuncSetAttribute(moe_gateup_hmma, cudaFuncAttributeMaxDynamicSharedMemorySize,
                             STAGES * GU_STRIDE + 1024);
        cudaFuncSetAttribute(moe_down_hmma, cudaFuncAttributeMaxDynamicSharedMemorySize,
                             STAGES * DN_STRIDE + 1024);
        cudaGetSymbolAddress(&cnt_addr, g_cnt);
        attr_done = true;
    }

    cudaMemsetAsync(cnt_addr, 0, 16 * sizeof(int));

    prologue_kernel<<<T_TOK + NCV, 256>>>((const float4*)x, (const float4*)gup,
                                          rw, rb, (float4*)out);

    dim3 g1(T_TOK / 128, I_DIM / 64, N_EXP);
    moe_gateup_hmma<<<g1, 256, STAGES * GU_STRIDE + 1024>>>(gub, (const float4*)dwn);

    dim3 g2(T_TOK / 128, H_DIM / 64, N_EXP);
    moe_down_hmma<<<g2, 256, STAGES * DN_STRIDE + 1024>>>(dnb, out);
}

// round 16
// speedup vs baseline: 1.1539x; 1.0194x over previous
#include <cuda_runtime.h>
#include <cstdint>
#include <math.h>

#define T_TOK 1024
#define H_DIM 1024
#define N_EXP 8
#define I_DIM 1024
#define ALPHA 1.702f
#define LIMIT 7.0f

// ---------------- device scratch (no allocations allowed) --------------------
// g_cnt[0..7] = per-expert token counts, g_cnt[8] = convert ticket
__device__ int      g_cnt[16];
__device__ int      g_tok[N_EXP * T_TOK];
__device__ float    g_wt [N_EXP * T_TOK];
// fp16 operand planes, packed 2 elems per u32
__device__ __align__(16) uint32_t g_x_f16  [(size_t)T_TOK * H_DIM / 2];
__device__ __align__(16) uint32_t g_dwn_f16[(size_t)N_EXP * I_DIM * H_DIM / 2];
__device__ __align__(16) uint32_t g_act_f16[(size_t)N_EXP * T_TOK * I_DIM / 2];

// ---------------- helpers ----------------------------------------------------
__device__ __forceinline__ uint32_t smem_u32(const void* p) {
    uint32_t a;
    asm("{ .reg .u64 t; cvta.to.shared.u64 t, %1; cvt.u32.u64 %0, t; }"
        : "=r"(a) : "l"(p));
    return a;
}
__device__ __forceinline__ uint32_t swz128(uint32_t off) { return off ^ ((off >> 3) & 0x70); }
__device__ __forceinline__ uint32_t swz64 (uint32_t off) { return off ^ ((off >> 3) & 0x30); }

__device__ __forceinline__ uint32_t pack_f16x2(float a, float b) {
    uint32_t r;
    asm("cvt.rn.f16x2.f32 %0, %1, %2;" : "=r"(r) : "f"(b), "f"(a));  // a -> low half
    return r;
}

__device__ __forceinline__ void ldsm4(uint32_t* r, uint32_t a) {
    asm volatile("ldmatrix.sync.aligned.m8n8.x4.shared.b16 {%0,%1,%2,%3}, [%4];"
        : "=r"(r[0]), "=r"(r[1]), "=r"(r[2]), "=r"(r[3]) : "r"(a));
}
__device__ __forceinline__ void ldsm4t(uint32_t* r, uint32_t a) {
    asm volatile("ldmatrix.sync.aligned.m8n8.x4.trans.shared.b16 {%0,%1,%2,%3}, [%4];"
        : "=r"(r[0]), "=r"(r[1]), "=r"(r[2]), "=r"(r[3]) : "r"(a));
}
__device__ __forceinline__ void mma16816(float* c, const uint32_t* a, uint32_t b0, uint32_t b1) {
    asm volatile("mma.sync.aligned.m16n8k16.row.col.f32.f16.f16.f32 "
        "{%0,%1,%2,%3}, {%4,%5,%6,%7}, {%8,%9}, {%0,%1,%2,%3};"
        : "+f"(c[0]), "+f"(c[1]), "+f"(c[2]), "+f"(c[3])
        : "r"(a[0]), "r"(a[1]), "r"(a[2]), "r"(a[3]), "r"(b0), "r"(b1));
}

#define CP16(dst, src) \
    asm volatile("cp.async.cg.shared.global [%0], [%1], 16;" :: "r"(dst), "l"(src) : "memory")
#define CP_COMMIT() asm volatile("cp.async.commit_group;" ::: "memory")
#define CP_WAIT3()  asm volatile("cp.async.wait_group 3;" ::: "memory")

// sizes in "2x float4" (32B src) units
#define NX2 (T_TOK * H_DIM / 8)
#define ND2 (N_EXP * I_DIM * H_DIM / 8)
#define NCV ((NX2 + 255) / 256)
#define ND_CHUNKS (ND2 / 256)

// ---------------- fused prologue: router + x convert -------------------------
__global__ void prologue_kernel(const float4* __restrict__ x4,
                                const float* __restrict__ rw,
                                const float* __restrict__ rb,
                                float4* __restrict__ out) {
    const int tid = threadIdx.x;
    if (blockIdx.x < T_TOK) {
        // ---- router for token t (256 threads) + zero out row ----
        const int t = blockIdx.x;
        out[t * 256 + tid] = make_float4(0.f, 0.f, 0.f, 0.f);

        __shared__ float s[N_EXP][256];
        __shared__ float s_log[N_EXP];
        const float* xr = (const float*)(x4) + (size_t)t * H_DIM;
        float p[N_EXP];
#pragma unroll
        for (int e = 0; e < N_EXP; e++) p[e] = 0.0f;
#pragma unroll
        for (int q = 0; q < 4; q++) {
            int h = tid + q * 256;
            float xv = xr[h];
#pragma unroll
            for (int e = 0; e < N_EXP; e++) p[e] += xv * rw[e * H_DIM + h];
        }
#pragma unroll
        for (int e = 0; e < N_EXP; e++) s[e][tid] = p[e];
        __syncthreads();
        const int wid = tid >> 5, lane = tid & 31;
        {
            float v = 0.0f;
#pragma unroll
            for (int j = 0; j < 8; j++) v += s[wid][lane + 32 * j];
#pragma unroll
            for (int o = 16; o > 0; o >>= 1) v += __shfl_xor_sync(0xFFFFFFFFu, v, o);
            if (lane == 0) s_log[wid] = v + rb[wid];
        }
        __syncthreads();
        if (tid == 0) {
            float l[N_EXP], mx = -1e30f;
#pragma unroll
            for (int e = 0; e < N_EXP; e++) { l[e] = s_log[e]; mx = fmaxf(mx, l[e]); }
            float den = 0.0f, sc[N_EXP];
#pragma unroll
            for (int e = 0; e < N_EXP; e++) { sc[e] = expf(l[e] - mx); den += sc[e]; }
            float inv = 1.0f / den;
#pragma unroll
            for (int e = 0; e < N_EXP; e++) sc[e] *= inv;
            int i0 = 0;
#pragma unroll
            for (int e = 1; e < N_EXP; e++) if (sc[e] > sc[i0]) i0 = e;
            int i1 = (i0 == 0) ? 1 : 0;
#pragma unroll
            for (int e = 0; e < N_EXP; e++) if (e != i0 && sc[e] > sc[i1]) i1 = e;
            int p0 = atomicAdd(&g_cnt[i0], 1);
            g_tok[i0 * T_TOK + p0] = t; g_wt[i0 * T_TOK + p0] = sc[i0];
            int p1 = atomicAdd(&g_cnt[i1], 1);
            g_tok[i1 * T_TOK + p1] = t; g_wt[i1 * T_TOK + p1] = sc[i1];
        }
        return;
    }
    // ---- convert x only: 32B fp32 -> 16B fp16 per thread ----
    int i = (blockIdx.x - T_TOK) * 256 + tid;
    if (i >= NX2) return;
    uint2* dst = (uint2*)g_x_f16;
    int j = i * 2;
    float4 v0 = x4[j];
    float4 v1 = x4[j + 1];
    dst[j]     = make_uint2(pack_f16x2(v0.x, v0.y), pack_f16x2(v0.z, v0.w));
    dst[j + 1] = make_uint2(pack_f16x2(v1.x, v1.y), pack_f16x2(v1.z, v1.w));
}

// ---------------- kernel 2: gate_up HMMA (fp16 A via cp.async; B inline-
// converted from fp32 global). BK=32, 5-stage, A depth-3, B depth-1 staged.
// Stage (16KB): A 8KB (128 rows x 64B, SW64), BG 4KB, BU 4KB (32 k x 128B, SW128)
// Dead blocks (m0 >= cnt) convert down_proj fp32->fp16 via ticket queue.
#define GU_A      0
#define GU_BG     8192
#define GU_BU     12288
#define GU_STRIDE 16384
#define STAGES    5
#define N_ITERS   32

__global__ __launch_bounds__(256, 2)
void moe_gateup_hmma(const float* __restrict__ gup,
                     const float* __restrict__ gub,
                     const float4* __restrict__ dwn) {
    const int e   = blockIdx.z;
    const int cnt = g_cnt[e];
    const int m0  = blockIdx.x * 128;
    const int tid = threadIdx.x;

    if (m0 >= cnt) {
        // ---- recycled block: convert down_proj chunks ----
        __shared__ int s_c;
        uint2* dst = (uint2*)g_dwn_f16;
        for (;;) {
            if (tid == 0) s_c = atomicAdd(&g_cnt[8], 1);
            __syncthreads();
            int c = s_c;
            __syncthreads();
            if (c >= ND_CHUNKS) return;
            int j = (c * 256 + tid) * 2;
            float4 v0 = dwn[j];
            float4 v1 = dwn[j + 1];
            dst[j]     = make_uint2(pack_f16x2(v0.x, v0.y), pack_f16x2(v0.z, v0.w));
            dst[j + 1] = make_uint2(pack_f16x2(v1.x, v1.y), pack_f16x2(v1.z, v1.w));
        }
    }
    const int n0 = blockIdx.y * 64;

    extern __shared__ char dsm[];
    __shared__ int s_tok[128];
    const uint32_t dbase = (smem_u32(dsm) + 1023u) & ~1023u;

    const int lane = tid & 31, wid = tid >> 5;
    const int mw = wid >> 1, nw = wid & 1;

    if (tid < 128) {
        int gm = m0 + tid;
        s_tok[tid] = (gm < cnt) ? g_tok[e * T_TOK + gm] : g_tok[e * T_TOK];
    }
    __syncthreads();

    // A loader (cp.async): rows rA, rA+64; 16B chunk pA
    const int rA = tid >> 2, pA = tid & 3;
    const int tA0 = s_tok[rA], tA1 = s_tok[rA + 64];
    const uint32_t dA0 = swz64(rA * 64 + pA * 16);
    const uint32_t dA1 = swz64((rA + 64) * 64 + pA * 16);

    // B loader (fp32 LDG + convert + STS): k-row kB (0..31), 32B fp32 chunk pB
    const int kB = tid >> 3, pB = tid & 7;
    const float* gupe = gup + (size_t)e * (H_DIM * 2 * I_DIM);
    const uint32_t sB  = swz128(kB * 128 + pB * 16);

#define GU_ISSUE_A(s_) do { if ((s_) < N_ITERS) {                                            \
    uint32_t bb = dbase + ((s_) % STAGES) * GU_STRIDE;                                       \
    int kh = (s_) * 16;                                                                      \
    CP16(bb + GU_A + dA0, g_x_f16 + (size_t)tA0 * 512 + kh + pA * 4);                        \
    CP16(bb + GU_A + dA1, g_x_f16 + (size_t)tA1 * 512 + kh + pA * 4);                        \
} CP_COMMIT(); } while (0)

    // B staging registers: 8 gate fp32 + 8 up fp32
    float4 bgs0, bgs1, bus0, bus1;
#define GU_LDG_B(s_) do { if ((s_) < N_ITERS) {                                              \
    const float* bp = gupe + (size_t)((s_) * 32 + kB) * (2 * I_DIM) + n0 + pB * 8;           \
    bgs0 = *(const float4*)bp;       bgs1 = *(const float4*)(bp + 4);                        \
    bus0 = *(const float4*)(bp + I_DIM); bus1 = *(const float4*)(bp + I_DIM + 4);            \
} } while (0)

#define GU_STS_B(s_) do {                                                                    \
    uint32_t bb = dbase + ((s_) % STAGES) * GU_STRIDE;                                       \
    uint4 wg = make_uint4(pack_f16x2(bgs0.x, bgs0.y), pack_f16x2(bgs0.z, bgs0.w),            \
                          pack_f16x2(bgs1.x, bgs1.y), pack_f16x2(bgs1.z, bgs1.w));           \
    uint4 wu = make_uint4(pack_f16x2(bus0.x, bus0.y), pack_f16x2(bus0.z, bus0.w),            \
                          pack_f16x2(bus1.x, bus1.y), pack_f16x2(bus1.z, bus1.w));           \
    *(uint4*)(dsm + (dbase - smem_u32(dsm)) + ((s_) % STAGES) * GU_STRIDE + GU_BG + sB) = wg;\
    *(uint4*)(dsm + (dbase - smem_u32(dsm)) + ((s_) % STAGES) * GU_STRIDE + GU_BU + sB) = wu;\
    (void)bb;                                                                                \
} while (0)

    float cg[2][4][4], cu[2][4][4];
#pragma unroll
    for (int a = 0; a < 2; a++)
#pragma unroll
        for (int b = 0; b < 4; b++)
#pragma unroll
            for (int c = 0; c < 4; c++) { cg[a][b][c] = 0.f; cu[a][b][c] = 0.f; }

    GU_ISSUE_A(0);
    GU_ISSUE_A(1);
    GU_ISSUE_A(2);
    GU_LDG_B(0);

#pragma unroll 1
    for (int it = 0; it < N_ITERS; ++it) {
        GU_STS_B(it);            // convert staged fp32 -> fp16 SMEM (buffer it%5)
        GU_LDG_B(it + 1);        // stage next B (covered by full iter latency)
        GU_ISSUE_A(it + 3);
        CP_WAIT3();
        __syncthreads();
        uint32_t base = dbase + (it % STAGES) * GU_STRIDE;
#pragma unroll
        for (int s = 0; s < 2; s++) {
            uint32_t am[2][4];
#pragma unroll
            for (int mt = 0; mt < 2; mt++) {
                uint32_t row = mw * 32 + mt * 16 + (lane & 15);
                uint32_t co  = s * 32 + ((lane >> 4) << 4);
                ldsm4(am[mt], base + GU_A + swz64(row * 64 + co));
            }
            uint32_t krow = s * 16 + (lane & 15);
            uint32_t ccol = nw * 64 + ((lane >> 4) << 4);
            uint32_t bg[8], bu[8];
#pragma unroll
            for (int h = 0; h < 2; h++) {
                ldsm4t(bg + 4 * h, base + GU_BG + swz128(krow * 128 + ccol + h * 32));
                ldsm4t(bu + 4 * h, base + GU_BU + swz128(krow * 128 + ccol + h * 32));
            }
#pragma unroll
            for (int mt = 0; mt < 2; mt++)
#pragma unroll
                for (int nf = 0; nf < 4; nf++) {
                    mma16816(cg[mt][nf], am[mt], bg[2*nf], bg[2*nf+1]);
                    mma16816(cu[mt][nf], am[mt], bu[2*nf], bu[2*nf+1]);
                }
        }
        __syncthreads();   // protect buffer (it%5) writes next loop vs readers
    }
#undef GU_ISSUE_A
#undef GU_LDG_B
#undef GU_STS_B

    // epilogue: bias + clamped GLU -> g_act (packed fp16)
    const float* gb = gub + e * 2 * I_DIM;
#pragma unroll
    for (int mt = 0; mt < 2; mt++)
#pragma unroll
        for (int r = 0; r < 2; r++) {
            int slot = m0 + mw * 32 + mt * 16 + (lane >> 2) + r * 8;
            if (slot >= cnt) continue;
            size_t abase = ((size_t)(e * T_TOK + slot) * I_DIM) >> 1;
#pragma unroll
            for (int nf = 0; nf < 4; nf++) {
                int col = n0 + nw * 32 + nf * 8 + (lane & 3) * 2;
                float g0 = cg[mt][nf][2 * r]     + gb[col];
                float g1 = cg[mt][nf][2 * r + 1] + gb[col + 1];
                float u0 = cu[mt][nf][2 * r]     + gb[I_DIM + col];
                float u1 = cu[mt][nf][2 * r + 1] + gb[I_DIM + col + 1];
                g0 = fminf(g0, LIMIT); g1 = fminf(g1, LIMIT);
                u0 = fminf(fmaxf(u0, -LIMIT), LIMIT);
                u1 = fminf(fmaxf(u1, -LIMIT), LIMIT);
                float a0 = (u0 + 1.0f) * (g0 / (1.0f + __expf(-ALPHA * g0)));
                float a1 = (u1 + 1.0f) * (g1 / (1.0f + __expf(-ALPHA * g1)));
                g_act_f16[abase + (col >> 1)] = pack_f16x2(a0, a1);
            }
        }
}

// ---------------- kernel 3: down HMMA (fp16, BK=32, 5-stage, depth-3) --------
// Stage (12KB): A 8KB (SW64), B 4KB (SW128). (R11 inner loop, proven 102.5)
#define DN_A      0
#define DN_B      8192
#define DN_STRIDE 12288

__global__ __launch_bounds__(256, 2)
void moe_down_hmma(const float* __restrict__ dnb, float* __restrict__ out) {
    const int e   = blockIdx.z;
    const int cnt = g_cnt[e];
    const int m0  = blockIdx.x * 128;
    if (m0 >= cnt) return;
    const int n0  = blockIdx.y * 64;

    extern __shared__ char dsm[];
    const uint32_t dbase = (smem_u32(dsm) + 1023u) & ~1023u;

    const int tid = threadIdx.x, lane = tid & 31, wid = tid >> 5;
    const int mw = wid >> 1, nw = wid & 1;

    const int rA = tid >> 2, pA = tid & 3;
    const int kB = tid >> 3, pB = tid & 7;
    const size_t a0 = (size_t)(e * T_TOK + m0 + rA) * 512;
    const size_t a1 = (size_t)(e * T_TOK + m0 + rA + 64) * 512;
    const size_t dwb = (size_t)e * (I_DIM * H_DIM / 2);
    const uint32_t dA0 = swz64(rA * 64 + pA * 16);
    const uint32_t dA1 = swz64((rA + 64) * 64 + pA * 16);
    const uint32_t dB  = swz128(kB * 128 + pB * 16);

#define DN_ISSUE(s_) do { if ((s_) < N_ITERS) {                                              \
    uint32_t bb = dbase + ((s_) % STAGES) * DN_STRIDE;                                       \
    int kh = (s_) * 16;                                                                      \
    CP16(bb + DN_A + dA0, g_act_f16 + a0 + kh + pA * 4);                                     \
    CP16(bb + DN_A + dA1, g_act_f16 + a1 + kh + pA * 4);                                     \
    size_t bro = dwb + (size_t)((s_) * 32 + kB) * 512 + (n0 >> 1) + pB * 4;                  \
    CP16(bb + DN_B + dB, g_dwn_f16 + bro);                                                   \
} CP_COMMIT(); } while (0)

    float cd[2][4][4];
#pragma unroll
    for (int a = 0; a < 2; a++)
#pragma unroll
        for (int b = 0; b < 4; b++)
#pragma unroll
            for (int c = 0; c < 4; c++) cd[a][b][c] = 0.f;

    DN_ISSUE(0);
    DN_ISSUE(1);
    DN_ISSUE(2);

#pragma unroll 1
    for (int it = 0; it < N_ITERS; ++it) {
        DN_ISSUE(it + 3);
        CP_WAIT3();
        __syncthreads();
        uint32_t base = dbase + (it % STAGES) * DN_STRIDE;
#pragma unroll
        for (int s = 0; s < 2; s++) {
            uint32_t am[2][4];
#pragma unroll
            for (int mt = 0; mt < 2; mt++) {
                uint32_t row = mw * 32 + mt * 16 + (lane & 15);
                uint32_t co  = s * 32 + ((lane >> 4) << 4);
                ldsm4(am[mt], base + DN_A + swz64(row * 64 + co));
            }
            uint32_t krow = s * 16 + (lane & 15);
            uint32_t ccol = nw * 64 + ((lane >> 4) << 4);
            uint32_t bb[8];
#pragma unroll
            for (int h = 0; h < 2; h++)
                ldsm4t(bb + 4 * h, base + DN_B + swz128(krow * 128 + ccol + h * 32));
#pragma unroll
            for (int mt = 0; mt < 2; mt++)
#pragma unroll
                for (int nf = 0; nf < 4; nf++)
                    mma16816(cd[mt][nf], am[mt], bb[2*nf], bb[2*nf+1]);
        }
    }
#undef DN_ISSUE

    const float* db = dnb + e * H_DIM;
#pragma unroll
    for (int mt = 0; mt < 2; mt++)
#pragma unroll
        for (int r = 0; r < 2; r++) {
            int slot = m0 + mw * 32 + mt * 16 + (lane >> 2) + r * 8;
            if (slot >= cnt) continue;
            int   tok = g_tok[e * T_TOK + slot];
            float w   = g_wt [e * T_TOK + slot];
            float* op = out + (size_t)tok * H_DIM;
#pragma unroll
            for (int nf = 0; nf < 4; nf++) {
                int col = n0 + nw * 32 + nf * 8 + (lane & 3) * 2;
                float v0 = (cd[mt][nf][2 * r]     + db[col])     * w;
                float v1 = (cd[mt][nf][2 * r + 1] + db[col + 1]) * w;
                atomicAdd(op + col,     v0);
                atomicAdd(op + col + 1, v1);
            }
        }
}

// ---------------- launch -----------------------------------------------------
extern "C" void kernel_launch(void* const* d_in, const int* in_sizes, int n_in,
                              void* d_out, int out_size) {
    const float* x   = (const float*)d_in[0];
    const float* rw  = (const float*)d_in[1];
    const float* rb  = (const float*)d_in[2];
    const float* gup = (const float*)d_in[3];
    const float* gub = (const float*)d_in[4];
    const float* dwn = (const float*)d_in[5];
    const float* dnb = (const float*)d_in[6];
    float* out = (float*)d_out;

    static bool attr_done = false;
    static void* cnt_addr = nullptr;
    if (!attr_done) {
        cudaFuncSetAttribute(moe_gateup_hmma, cudaFuncAttributeMaxDynamicSharedMemorySize,
                             STAGES * GU_STRIDE + 1024);
        cudaFuncSetAttribute(moe_down_hmma, cudaFuncAttributeMaxDynamicSharedMemorySize,
                             STAGES * DN_STRIDE + 1024);
        cudaGetSymbolAddress(&cnt_addr, g_cnt);
        attr_done = true;
    }

    cudaMemsetAsync(cnt_addr, 0, 16 * sizeof(int));

    prologue_kernel<<<T_TOK + NCV, 256>>>((const float4*)x, rw, rb, (float4*)out);

    dim3 g1(T_TOK / 128, I_DIM / 64, N_EXP);
    moe_gateup_hmma<<<g1, 256, STAGES * GU_STRIDE + 1024>>>(gup, gub, (const float4*)dwn);

    dim3 g2(T_TOK / 128, H_DIM / 64, N_EXP);
    moe_down_hmma<<<g2, 256, STAGES * DN_STRIDE + 1024>>>(dnb, out);
}